// round 14
// baseline (speedup 1.0000x reference)
#include <cuda_runtime.h>
#include <cuda_bf16.h>
#include <cstdint>

// ============================================================================
// out_f32[m, n] = f32( bf16(sum_k bf16(x[m,k]) * (bf16(w_fp8[n,k])*bf16(sc[n]))) + bf16(bias[n]) )
// M = B*S = 4096, N = OUT = 4096, K = IN = 4096. OUTPUT FP32.
// cg2 256x256 pair tiles, warp-specialized MMA issue (R13). This round:
// STAGES 3 -> 6 (SMEM ~193KB, occ 1): loaders run 5 chunks ahead, the cg2
// pair owns its SM-pair's tensor unit exclusively, and cross-CTA load skew is
// absorbed by the deep buffer instead of stalling every chunk.
// tcgen05 only in the arch-specific pass; generic pass gets a scalar fallback.
// ============================================================================

#if defined(__CUDA_ARCH__) && \
    (defined(__CUDA_ARCH_FEAT_SM103_ALL) || defined(__CUDA_ARCH_FEAT_SM100_ALL) || \
     defined(__CUDA_ARCH_FEAT_SM101_ALL) || defined(__CUDA_ARCH_SPECIFIC__) || \
     defined(__CUDA_ARCH_FAMILY_SPECIFIC__))
#define HAS_TCGEN05 1
#else
#define HAS_TCGEN05 0
#endif

static constexpr int Mdim = 4096, Ndim = 4096, Kdim = 4096;
static constexpr int MT = 256, NT = 256, KC = 64;        // pair tile; KC=64 bf16=128B
static constexpr int STAGES = 6;                          // deep pipeline, occ 1
static constexpr int NCHUNK = Kdim / KC;                  // 64
static constexpr int STAGE_BYTES = 128 * 128;             // 128 rows x 128B per CTA
static constexpr int NTHREADS = 160;                      // 4 loader warps + 1 MMA warp

static constexpr int SMEM_TMEM_PTR = 0;
static constexpr int SMEM_EMPTY = 64;                     // 6 x 8B (commit multicast)
static constexpr int SMEM_FULL = 128;                     // 6 x 8B (rank0, count=256)
static constexpr int SMEM_A = 1024;
static constexpr int SMEM_B = SMEM_A + STAGES * STAGE_BYTES;
static constexpr int SMEM_TOTAL = SMEM_B + STAGES * STAGE_BYTES;  // ~193 KB -> 1 CTA/SM

// idesc kind::f16 cg2: dtype=F32(1<<4), atype=BF16(1<<7), btype=BF16(1<<10),
// N=256 -> (256/8)<<17, M=256 -> (256/16)<<24
static constexpr uint32_t IDESC_CG2 =
    (1u << 4) | (1u << 7) | (1u << 10) | ((NT / 8) << 17) | ((MT / 16) << 24);

// bf16 scratch (allowed: __device__ global arrays)
__device__ __nv_bfloat16 g_x[(size_t)Mdim * Kdim];
__device__ __nv_bfloat16 g_w[(size_t)Ndim * Kdim];

// ============================================================================
// PTX helpers
// ============================================================================

__device__ __forceinline__ uint32_t smem_u32(const void* p) {
    uint32_t a;
    asm("{ .reg .u64 t; cvta.to.shared.u64 t, %1; cvt.u32.u64 %0, t; }"
        : "=r"(a) : "l"(p));
    return a;
}

__device__ __forceinline__ uint32_t ctarank() {
    uint32_t r;
    asm("mov.u32 %0, %%cluster_ctarank;" : "=r"(r));
    return r;
}

__device__ __forceinline__ void cluster_sync() {
    asm volatile("barrier.cluster.arrive.aligned;" ::: "memory");
    asm volatile("barrier.cluster.wait.aligned;" ::: "memory");
}

__device__ __forceinline__ void cp_async16(uint32_t s, const void* g) {
    asm volatile("cp.async.cg.shared.global [%0], [%1], 16;" :: "r"(s), "l"(g));
}
__device__ __forceinline__ void cp_commit() {
    asm volatile("cp.async.commit_group;" ::: "memory");
}
template <int N>
__device__ __forceinline__ void cp_wait() {
    asm volatile("cp.async.wait_group %0;" :: "n"(N) : "memory");
}

#if HAS_TCGEN05
__device__ __forceinline__ uint32_t elect_one() {
    uint32_t pred;
    asm volatile(
        "{\n\t.reg .pred p;\n\t"
        "elect.sync _|p, 0xFFFFFFFF;\n\t"
        "selp.b32 %0, 1, 0, p;\n\t}"
        : "=r"(pred));
    return pred;
}

__device__ __forceinline__ void mbar_init(uint32_t addr, uint32_t count) {
    asm volatile("mbarrier.init.shared.b64 [%0], %1;" :: "r"(addr), "r"(count) : "memory");
}
__device__ __forceinline__ void mbar_inval(uint32_t addr) {
    asm volatile("mbarrier.inval.shared.b64 [%0];" :: "r"(addr) : "memory");
}
__device__ __forceinline__ void mbar_wait(uint32_t addr, uint32_t parity) {
    asm volatile(
        "{\n\t.reg .pred P;\n\t"
        "WAIT_%=:\n\t"
        "mbarrier.try_wait.parity.acquire.cta.shared::cta.b64 P, [%0], %1, 0x989680;\n\t"
        "@P bra DONE_%=;\n\t"
        "bra WAIT_%=;\n\t"
        "DONE_%=:\n\t}"
        :: "r"(addr), "r"(parity) : "memory");
}

__device__ __forceinline__ void mbar_wait_cluster(uint32_t addr, uint32_t parity) {
    asm volatile(
        "{\n\t.reg .pred P;\n\t"
        "WAIT_%=:\n\t"
        "mbarrier.try_wait.parity.acquire.cluster.shared::cta.b64 P, [%0], %1, 0x989680;\n\t"
        "@P bra DONE_%=;\n\t"
        "bra WAIT_%=;\n\t"
        "DONE_%=:\n\t}"
        :: "r"(addr), "r"(parity) : "memory");
}

// Arrive on the mbarrier at the same SMEM offset in cluster CTA `target_rank`.
__device__ __forceinline__ void mbar_arrive_cluster(uint32_t local_addr, uint32_t target_rank) {
    asm volatile(
        "{\n\t.reg .b32 ra;\n\t"
        "mapa.shared::cluster.u32 ra, %0, %1;\n\t"
        "mbarrier.arrive.shared::cluster.b64 _, [ra];\n\t}"
        :: "r"(local_addr), "r"(target_rank) : "memory");
}

__device__ __forceinline__ void fence_proxy_async_cta() {
    asm volatile("fence.proxy.async.shared::cta;" ::: "memory");
}

// SW128 K-major descriptor: layout=2, version=1, SBO=64, LBO=1
__device__ __forceinline__ uint64_t make_desc(uint32_t addr) {
    const uint64_t base =
        (uint64_t(2) << 61) | (uint64_t(1) << 46) | (uint64_t(64) << 32) | (uint64_t(1) << 16);
    return base | ((uint64_t)(addr >> 4) & 0x3FFF);
}

// cg2 bf16 SS MMA
__device__ __forceinline__ void mma_f16_ss_cg2(uint32_t d_tmem, uint64_t a_desc,
                                               uint64_t b_desc, uint32_t idesc,
                                               uint32_t enable) {
    asm volatile(
        "{\n\t.reg .pred p;\n\t"
        "setp.ne.u32 p, %6, 0;\n\t"
        "tcgen05.mma.cta_group::2.kind::f16 [%0], %1, %2, %3, "
        "{%4, %4, %4, %4, %4, %4, %4, %4}, p;\n\t}"
        :: "r"(d_tmem), "l"(a_desc), "l"(b_desc), "r"(idesc),
           "r"(0u), "r"(0u), "r"(enable)
        : "memory");
}

__device__ __forceinline__ void tc_commit_mcast_cg2(uint32_t mbar, uint16_t mask) {
    asm volatile(
        "tcgen05.commit.cta_group::2.mbarrier::arrive::one.shared::cluster.multicast::cluster.b64 [%0], %1;"
        :: "r"(mbar), "h"(mask) : "memory");
}

#define TC_ALLOC_CG2(smem_addr, ncols) \
    asm volatile("tcgen05.alloc.cta_group::2.sync.aligned.shared::cta.b32 [%0], %1;" \
                 :: "r"(smem_addr), "r"((uint32_t)(ncols)) : "memory")
#define TC_DEALLOC_CG2(tmem, ncols) \
    asm volatile("tcgen05.dealloc.cta_group::2.sync.aligned.b32 %0, %1;" \
                 :: "r"(tmem), "r"((uint32_t)(ncols)))
#define TC_RELINQUISH_CG2() \
    asm volatile("tcgen05.relinquish_alloc_permit.cta_group::2.sync.aligned;")
#define TC_FENCE_AFTER() asm volatile("tcgen05.fence::after_thread_sync;" ::: "memory")
#define TC_WAIT_LD() asm volatile("tcgen05.wait::ld.sync.aligned;" ::: "memory")

#define LDTM_X32(r, addr) \
    asm volatile( \
        "tcgen05.ld.sync.aligned.32x32b.x32.b32 " \
        "{%0, %1, %2, %3, %4, %5, %6, %7, " \
        " %8, %9, %10, %11, %12, %13, %14, %15, " \
        " %16, %17, %18, %19, %20, %21, %22, %23, " \
        " %24, %25, %26, %27, %28, %29, %30, %31}, [%32];" \
        : "=r"((r)[0]),  "=r"((r)[1]),  "=r"((r)[2]),  "=r"((r)[3]), \
          "=r"((r)[4]),  "=r"((r)[5]),  "=r"((r)[6]),  "=r"((r)[7]), \
          "=r"((r)[8]),  "=r"((r)[9]),  "=r"((r)[10]), "=r"((r)[11]), \
          "=r"((r)[12]), "=r"((r)[13]), "=r"((r)[14]), "=r"((r)[15]), \
          "=r"((r)[16]), "=r"((r)[17]), "=r"((r)[18]), "=r"((r)[19]), \
          "=r"((r)[20]), "=r"((r)[21]), "=r"((r)[22]), "=r"((r)[23]), \
          "=r"((r)[24]), "=r"((r)[25]), "=r"((r)[26]), "=r"((r)[27]), \
          "=r"((r)[28]), "=r"((r)[29]), "=r"((r)[30]), "=r"((r)[31]) \
        : "r"(addr))
#endif  // HAS_TCGEN05

// ============================================================================
// Conversion kernels (arch-neutral)
// ============================================================================

__global__ void __launch_bounds__(256) cvt_x_kernel(const float* __restrict__ x) {
    size_t i = ((size_t)blockIdx.x * blockDim.x + threadIdx.x) * 4;
    float4 v = *reinterpret_cast<const float4*>(x + i);
    *reinterpret_cast<__nv_bfloat162*>(&g_x[i])     = __floats2bfloat162_rn(v.x, v.y);
    *reinterpret_cast<__nv_bfloat162*>(&g_x[i + 2]) = __floats2bfloat162_rn(v.z, v.w);
}

__global__ void __launch_bounds__(256) cvt_w_kernel(const float* __restrict__ wq,
                                                    const float* __restrict__ sc) {
    size_t i = ((size_t)blockIdx.x * blockDim.x + threadIdx.x) * 4;
    int o = (int)(i >> 12);  // row = i / 4096
    __nv_bfloat16 s = __float2bfloat16(sc[o]);
    float4 v = *reinterpret_cast<const float4*>(wq + i);
    __nv_bfloat16 h0 = __hmul(__float2bfloat16(v.x), s);
    __nv_bfloat16 h1 = __hmul(__float2bfloat16(v.y), s);
    __nv_bfloat16 h2 = __hmul(__float2bfloat16(v.z), s);
    __nv_bfloat16 h3 = __hmul(__float2bfloat16(v.w), s);
    *reinterpret_cast<__nv_bfloat162*>(&g_w[i])     = __halves2bfloat162(h0, h1);
    *reinterpret_cast<__nv_bfloat162*>(&g_w[i + 2]) = __halves2bfloat162(h2, h3);
}

// ============================================================================
// GEMM kernel: 256x256 pair tile (cg2), 6-stage pipeline, occ 1.
// ============================================================================

__global__ void __launch_bounds__(NTHREADS) __cluster_dims__(2, 1, 1)
gemm_kernel(float* __restrict__ out, const float* __restrict__ bias) {
    extern __shared__ char smem[];
    int tid = threadIdx.x;

#if HAS_TCGEN05
    uint32_t sb = smem_u32(smem);
    int wid = tid >> 5;
    int lid = tid & 31;
    uint32_t rank = ctarank();
    int n0t = (blockIdx.x >> 1) * NT;          // pair's N origin
    int m0t = blockIdx.y * MT;                 // pair's M origin

    if (tid == 0) {
        #pragma unroll
        for (int s = 0; s < STAGES; s++) {
            mbar_init(sb + SMEM_EMPTY + 8 * s, 1);     // MMA commit (multicast)
            mbar_init(sb + SMEM_FULL + 8 * s, 256);    // 128 loaders x 2 CTAs
        }
    }
    if (wid == 0) {
        TC_ALLOC_CG2(sb + SMEM_TMEM_PTR, 256);
    }
    __syncthreads();
    uint32_t tmem;
    asm volatile("ld.shared.b32 %0, [%1];" : "=r"(tmem) : "r"(sb + SMEM_TMEM_PTR));

    // All mbarriers (esp. rank0's full[]) must be init'd cluster-wide before use.
    cluster_sync();

    if (wid < 4) {
        // ---------------- Loader role (threads 0..127) ----------------
        int lrow = tid >> 3;
        int lcolb = (tid & 7) * 16;
        uint32_t swc[8];
        #pragma unroll
        for (int j = 0; j < 8; j++) {
            uint32_t off = (uint32_t)(lrow + j * 16) * 128 + lcolb;
            swc[j] = off ^ ((off >> 3) & 0x70);
        }
        const __nv_bfloat16* xbase =
            g_x + (size_t)(m0t + rank * 128 + lrow) * Kdim + (tid & 7) * 8;
        const __nv_bfloat16* wbase =
            g_w + (size_t)(n0t + rank * 128 + lrow) * Kdim + (tid & 7) * 8;

        auto load_chunk = [&](int c, int s) {
            uint32_t abase = sb + SMEM_A + s * STAGE_BYTES;
            uint32_t bbase = sb + SMEM_B + s * STAGE_BYTES;
            const __nv_bfloat16* xa = xbase + c * KC;
            const __nv_bfloat16* wb = wbase + c * KC;
            #pragma unroll
            for (int j = 0; j < 8; j++) {
                cp_async16(abase + swc[j], xa + (size_t)j * 16 * Kdim);
                cp_async16(bbase + swc[j], wb + (size_t)j * 16 * Kdim);
            }
            cp_commit();
        };

        // Prologue: fill stages 0..4 (5 chunks ahead).
        load_chunk(0, 0);
        load_chunk(1, 1);
        load_chunk(2, 2);
        load_chunk(3, 3);
        load_chunk(4, 4);

        for (int c = 0; c < NCHUNK; c++) {
            int buf = c % STAGES;
            // Reuse gate: buffer (c+5)%6 == (c-1)%6 was consumed by chunk c-1.
            if (c + 5 < NCHUNK) {
                if (c >= 1) {
                    mbar_wait(sb + SMEM_EMPTY + 8 * ((c - 1) % STAGES),
                              ((c - 1) / STAGES) & 1);
                }
                load_chunk(c + 5, (c + 5) % STAGES);
            }
            // Wait for chunk c's cp.async group (up to 5 newer groups pending).
            int rem = NCHUNK - 1 - c;
            if (rem >= 5)      cp_wait<5>();
            else if (rem == 4) cp_wait<4>();
            else if (rem == 3) cp_wait<3>();
            else if (rem == 2) cp_wait<2>();
            else if (rem == 1) cp_wait<1>();
            else               cp_wait<0>();
            fence_proxy_async_cta();
            // Signal: this thread's slice of stage buf is in SMEM.
            mbar_arrive_cluster(sb + SMEM_FULL + 8 * buf, 0);
        }
    } else if (rank == 0) {
        // ---------------- MMA-issue role (warp 4, rank 0) ----------------
        if (elect_one()) {
            for (int c = 0; c < NCHUNK; c++) {
                int buf = c % STAGES;
                mbar_wait_cluster(sb + SMEM_FULL + 8 * buf, (c / STAGES) & 1);
                TC_FENCE_AFTER();
                uint64_t ad = make_desc(sb + SMEM_A + buf * STAGE_BYTES);
                uint64_t bd = make_desc(sb + SMEM_B + buf * STAGE_BYTES);
                #pragma unroll
                for (int kk = 0; kk < 4; kk++) {
                    mma_f16_ss_cg2(tmem, ad + kk * 2, bd + kk * 2, IDESC_CG2,
                                   (c == 0 && kk == 0) ? 0u : 1u);
                }
                tc_commit_mcast_cg2(sb + SMEM_EMPTY + 8 * buf, 0x3);
            }
        }
    }

    // Final commit (chunk NCHUNK-1) tracks all prior MMAs; delivered to both CTAs.
    mbar_wait(sb + SMEM_EMPTY + 8 * ((NCHUNK - 1) % STAGES), ((NCHUNK - 1) / STAGES) & 1);
    TC_FENCE_AFTER();

    // Epilogue (FP32): warps 0-3. Row = rank*128 + wid*32 + lid; 256 cols.
    if (wid < 4) {
        int mrow = m0t + (int)rank * 128 + wid * 32 + lid;
        float* orow = out + (size_t)mrow * Ndim + n0t;
        #pragma unroll
        for (int cb = 0; cb < NT; cb += 32) {
            uint32_t r[32];
            LDTM_X32(r, tmem + cb);
            TC_WAIT_LD();
            float vals[32];
            #pragma unroll
            for (int j = 0; j < 32; j++) {
                __nv_bfloat16 s = __hadd(__float2bfloat16(__uint_as_float(r[j])),
                                         __float2bfloat16(bias[n0t + cb + j]));
                vals[j] = __bfloat162float(s);
            }
            float4* dst = reinterpret_cast<float4*>(orow + cb);
            #pragma unroll
            for (int q = 0; q < 8; q++) {
                dst[q] = make_float4(vals[4 * q], vals[4 * q + 1],
                                     vals[4 * q + 2], vals[4 * q + 3]);
            }
        }
    }

    __syncthreads();
    if (tid == 0) {
        #pragma unroll
        for (int s = 0; s < STAGES; s++) {
            mbar_inval(sb + SMEM_EMPTY + 8 * s);
            mbar_inval(sb + SMEM_FULL + 8 * s);
        }
    }
    __syncthreads();
    if (wid == 0) {
        TC_RELINQUISH_CG2();
        TC_DEALLOC_CG2(tmem, 256);
    }
    cluster_sync();
#else
    // ---------- Generic fallback (no tcgen05 in this compile pass) ----------
    int rank = blockIdx.x & 1;
    int n0t = (blockIdx.x >> 1) * NT;
    int m0 = blockIdx.y * MT + rank * 128;

    for (int half = 0; half < 2; half++) {
        int n0 = n0t + half * 128;
        __nv_bfloat16* As = reinterpret_cast<__nv_bfloat16*>(smem);        // 128 x 32
        __nv_bfloat16* Bs = As + 128 * 32;                                 // 128 x 32
        int tr = tid >> 3;
        int tc = tid & 7;

        float acc[8][16];
        #pragma unroll
        for (int i = 0; i < 8; i++)
            #pragma unroll
            for (int j = 0; j < 16; j++) acc[i][j] = 0.0f;

        for (int kc = 0; kc < Kdim; kc += 32) {
            if (tid < 128) {
                const uint4* srcA = reinterpret_cast<const uint4*>(g_x + (size_t)(m0 + tid) * Kdim + kc);
                const uint4* srcB = reinterpret_cast<const uint4*>(g_w + (size_t)(n0 + tid) * Kdim + kc);
                uint4* dA = reinterpret_cast<uint4*>(As + tid * 32);
                uint4* dB = reinterpret_cast<uint4*>(Bs + tid * 32);
                #pragma unroll
                for (int j = 0; j < 4; j++) { dA[j] = srcA[j]; dB[j] = srcB[j]; }
            }
            __syncthreads();

            if (tid < 128) {
                for (int kk = 0; kk < 32; kk++) {
                    float a[8], b[16];
                    #pragma unroll
                    for (int i = 0; i < 8; i++)
                        a[i] = __bfloat162float(As[(tr * 8 + i) * 32 + kk]);
                    #pragma unroll
                    for (int j = 0; j < 16; j++)
                        b[j] = __bfloat162float(Bs[(tc * 16 + j) * 32 + kk]);
                    #pragma unroll
                    for (int i = 0; i < 8; i++)
                        #pragma unroll
                        for (int j = 0; j < 16; j++)
                            acc[i][j] = fmaf(a[i], b[j], acc[i][j]);
                }
            }
            __syncthreads();
        }

        if (tid < 128) {
            #pragma unroll
            for (int i = 0; i < 8; i++) {
                int m = m0 + tr * 8 + i;
                #pragma unroll
                for (int j = 0; j < 16; j++) {
                    int n = n0 + tc * 16 + j;
                    __nv_bfloat16 v = __hadd(__float2bfloat16(acc[i][j]),
                                             __float2bfloat16(bias[n]));
                    out[(size_t)m * Ndim + n] = __bfloat162float(v);
                }
            }
        }
        __syncthreads();
    }
#endif
}

// ============================================================================
// Launch
// ============================================================================

extern "C" void kernel_launch(void* const* d_in, const int* in_sizes, int n_in,
                              void* d_out, int out_size) {
    const float* x    = (const float*)d_in[0];   // [B, S, IN] f32
    const float* wq   = (const float*)d_in[1];   // [OUT, IN] f32 (fp8-representable)
    const float* ws   = (const float*)d_in[2];   // [OUT, 1] f32
    const float* bias = (const float*)d_in[3];   // [OUT] f32
    float* out = (float*)d_out;                  // [B, S, OUT] FP32

    // Convert inputs to bf16 scratch.
    {
        int threads = 256;
        int blocks = (Mdim * Kdim / 4) / threads;  // 16384
        cvt_x_kernel<<<blocks, threads>>>(x);
        cvt_w_kernel<<<blocks, threads>>>(wq, ws);
    }

    cudaFuncSetAttribute(gemm_kernel, cudaFuncAttributeMaxDynamicSharedMemorySize, SMEM_TOTAL);
    // Grid: x = 2 CTAs/pair * 16 n-tiles = 32, y = 16 m-tiles; cluster (2,1,1).
    dim3 grid(2 * (Ndim / NT), Mdim / MT);  // (32, 16)
    gemm_kernel<<<grid, NTHREADS, SMEM_TOTAL>>>(out, bias);
}

// round 15
// speedup vs baseline: 1.2117x; 1.2117x over previous
#include <cuda_runtime.h>
#include <cuda_bf16.h>
#include <cstdint>

// ============================================================================
// out_f32[m, n] = f32( bf16(sum_k bf16(x[m,k]) * (bf16(w_fp8[n,k])*bf16(sc[n]))) + bf16(bias[n]) )
// M = B*S = 4096, N = OUT = 4096, K = IN = 4096. OUTPUT FP32.
// R12-R14 pinned at ~190us GEMM regardless of sync structure => L2-BW bound
// (1 GB operand traffic @ ~5.4 TB/s achieved). This round: 256x512 pair tile
// (TMEM D = 512 cols, full capacity) -> chip traffic 768 MB.
//   - N=512 > idesc N-field => 2 x N=256 cg2 dispatches per K-step; half h
//     reads B rows [h*256, h*256+256) (per-CTA 128-row group at stage offset
//     h*16KB) and writes D cols [h*256, +256).
//   - 4 stages x 48KB = 192KB SMEM, occ 1, warp-specialized MMA issue.
// tcgen05 only in the arch-specific pass; generic pass gets a scalar fallback.
// ============================================================================

#if defined(__CUDA_ARCH__) && \
    (defined(__CUDA_ARCH_FEAT_SM103_ALL) || defined(__CUDA_ARCH_FEAT_SM100_ALL) || \
     defined(__CUDA_ARCH_FEAT_SM101_ALL) || defined(__CUDA_ARCH_SPECIFIC__) || \
     defined(__CUDA_ARCH_FAMILY_SPECIFIC__))
#define HAS_TCGEN05 1
#else
#define HAS_TCGEN05 0
#endif

static constexpr int Mdim = 4096, Ndim = 4096, Kdim = 4096;
static constexpr int MT = 256, NT = 512, KC = 64;        // pair tile; KC=64 bf16=128B
static constexpr int STAGES = 4;
static constexpr int NCHUNK = Kdim / KC;                  // 64
static constexpr int A_STAGE = 128 * 128;                 // 16KB: 128 A-rows x 128B
static constexpr int B_STAGE = 256 * 128;                 // 32KB: 2 x 128 B-rows x 128B
static constexpr int NTHREADS = 160;                      // 4 loader warps + 1 MMA warp

static constexpr int SMEM_TMEM_PTR = 0;
static constexpr int SMEM_EMPTY = 64;                     // 4 x 8B (commit multicast)
static constexpr int SMEM_FULL = 128;                     // 4 x 8B (rank0, count=256)
static constexpr int SMEM_A = 1024;
static constexpr int SMEM_B = SMEM_A + STAGES * A_STAGE;  // +64KB
static constexpr int SMEM_TOTAL = SMEM_B + STAGES * B_STAGE;  // ~193KB -> 1 CTA/SM

// idesc kind::f16 cg2, N=256 per dispatch: dtype=F32(1<<4), atype=BF16(1<<7),
// btype=BF16(1<<10), N=256 -> 32<<17, M=256 -> 16<<24
static constexpr uint32_t IDESC_CG2 =
    (1u << 4) | (1u << 7) | (1u << 10) | ((256 / 8) << 17) | ((MT / 16) << 24);

// bf16 scratch (allowed: __device__ global arrays)
__device__ __nv_bfloat16 g_x[(size_t)Mdim * Kdim];
__device__ __nv_bfloat16 g_w[(size_t)Ndim * Kdim];

// ============================================================================
// PTX helpers
// ============================================================================

__device__ __forceinline__ uint32_t smem_u32(const void* p) {
    uint32_t a;
    asm("{ .reg .u64 t; cvta.to.shared.u64 t, %1; cvt.u32.u64 %0, t; }"
        : "=r"(a) : "l"(p));
    return a;
}

__device__ __forceinline__ uint32_t ctarank() {
    uint32_t r;
    asm("mov.u32 %0, %%cluster_ctarank;" : "=r"(r));
    return r;
}

__device__ __forceinline__ void cluster_sync() {
    asm volatile("barrier.cluster.arrive.aligned;" ::: "memory");
    asm volatile("barrier.cluster.wait.aligned;" ::: "memory");
}

__device__ __forceinline__ void cp_async16(uint32_t s, const void* g) {
    asm volatile("cp.async.cg.shared.global [%0], [%1], 16;" :: "r"(s), "l"(g));
}
__device__ __forceinline__ void cp_commit() {
    asm volatile("cp.async.commit_group;" ::: "memory");
}
template <int N>
__device__ __forceinline__ void cp_wait() {
    asm volatile("cp.async.wait_group %0;" :: "n"(N) : "memory");
}

#if HAS_TCGEN05
__device__ __forceinline__ uint32_t elect_one() {
    uint32_t pred;
    asm volatile(
        "{\n\t.reg .pred p;\n\t"
        "elect.sync _|p, 0xFFFFFFFF;\n\t"
        "selp.b32 %0, 1, 0, p;\n\t}"
        : "=r"(pred));
    return pred;
}

__device__ __forceinline__ void mbar_init(uint32_t addr, uint32_t count) {
    asm volatile("mbarrier.init.shared.b64 [%0], %1;" :: "r"(addr), "r"(count) : "memory");
}
__device__ __forceinline__ void mbar_inval(uint32_t addr) {
    asm volatile("mbarrier.inval.shared.b64 [%0];" :: "r"(addr) : "memory");
}
__device__ __forceinline__ void mbar_wait(uint32_t addr, uint32_t parity) {
    asm volatile(
        "{\n\t.reg .pred P;\n\t"
        "WAIT_%=:\n\t"
        "mbarrier.try_wait.parity.acquire.cta.shared::cta.b64 P, [%0], %1, 0x989680;\n\t"
        "@P bra DONE_%=;\n\t"
        "bra WAIT_%=;\n\t"
        "DONE_%=:\n\t}"
        :: "r"(addr), "r"(parity) : "memory");
}

__device__ __forceinline__ void mbar_wait_cluster(uint32_t addr, uint32_t parity) {
    asm volatile(
        "{\n\t.reg .pred P;\n\t"
        "WAIT_%=:\n\t"
        "mbarrier.try_wait.parity.acquire.cluster.shared::cta.b64 P, [%0], %1, 0x989680;\n\t"
        "@P bra DONE_%=;\n\t"
        "bra WAIT_%=;\n\t"
        "DONE_%=:\n\t}"
        :: "r"(addr), "r"(parity) : "memory");
}

// Arrive on the mbarrier at the same SMEM offset in cluster CTA `target_rank`.
__device__ __forceinline__ void mbar_arrive_cluster(uint32_t local_addr, uint32_t target_rank) {
    asm volatile(
        "{\n\t.reg .b32 ra;\n\t"
        "mapa.shared::cluster.u32 ra, %0, %1;\n\t"
        "mbarrier.arrive.shared::cluster.b64 _, [ra];\n\t}"
        :: "r"(local_addr), "r"(target_rank) : "memory");
}

__device__ __forceinline__ void fence_proxy_async_cta() {
    asm volatile("fence.proxy.async.shared::cta;" ::: "memory");
}

// SW128 K-major descriptor: layout=2, version=1, SBO=64, LBO=1
__device__ __forceinline__ uint64_t make_desc(uint32_t addr) {
    const uint64_t base =
        (uint64_t(2) << 61) | (uint64_t(1) << 46) | (uint64_t(64) << 32) | (uint64_t(1) << 16);
    return base | ((uint64_t)(addr >> 4) & 0x3FFF);
}

// cg2 bf16 SS MMA
__device__ __forceinline__ void mma_f16_ss_cg2(uint32_t d_tmem, uint64_t a_desc,
                                               uint64_t b_desc, uint32_t idesc,
                                               uint32_t enable) {
    asm volatile(
        "{\n\t.reg .pred p;\n\t"
        "setp.ne.u32 p, %6, 0;\n\t"
        "tcgen05.mma.cta_group::2.kind::f16 [%0], %1, %2, %3, "
        "{%4, %4, %4, %4, %4, %4, %4, %4}, p;\n\t}"
        :: "r"(d_tmem), "l"(a_desc), "l"(b_desc), "r"(idesc),
           "r"(0u), "r"(0u), "r"(enable)
        : "memory");
}

__device__ __forceinline__ void tc_commit_mcast_cg2(uint32_t mbar, uint16_t mask) {
    asm volatile(
        "tcgen05.commit.cta_group::2.mbarrier::arrive::one.shared::cluster.multicast::cluster.b64 [%0], %1;"
        :: "r"(mbar), "h"(mask) : "memory");
}

#define TC_ALLOC_CG2(smem_addr, ncols) \
    asm volatile("tcgen05.alloc.cta_group::2.sync.aligned.shared::cta.b32 [%0], %1;" \
                 :: "r"(smem_addr), "r"((uint32_t)(ncols)) : "memory")
#define TC_DEALLOC_CG2(tmem, ncols) \
    asm volatile("tcgen05.dealloc.cta_group::2.sync.aligned.b32 %0, %1;" \
                 :: "r"(tmem), "r"((uint32_t)(ncols)))
#define TC_RELINQUISH_CG2() \
    asm volatile("tcgen05.relinquish_alloc_permit.cta_group::2.sync.aligned;")
#define TC_FENCE_AFTER() asm volatile("tcgen05.fence::after_thread_sync;" ::: "memory")
#define TC_WAIT_LD() asm volatile("tcgen05.wait::ld.sync.aligned;" ::: "memory")

#define LDTM_X32(r, addr) \
    asm volatile( \
        "tcgen05.ld.sync.aligned.32x32b.x32.b32 " \
        "{%0, %1, %2, %3, %4, %5, %6, %7, " \
        " %8, %9, %10, %11, %12, %13, %14, %15, " \
        " %16, %17, %18, %19, %20, %21, %22, %23, " \
        " %24, %25, %26, %27, %28, %29, %30, %31}, [%32];" \
        : "=r"((r)[0]),  "=r"((r)[1]),  "=r"((r)[2]),  "=r"((r)[3]), \
          "=r"((r)[4]),  "=r"((r)[5]),  "=r"((r)[6]),  "=r"((r)[7]), \
          "=r"((r)[8]),  "=r"((r)[9]),  "=r"((r)[10]), "=r"((r)[11]), \
          "=r"((r)[12]), "=r"((r)[13]), "=r"((r)[14]), "=r"((r)[15]), \
          "=r"((r)[16]), "=r"((r)[17]), "=r"((r)[18]), "=r"((r)[19]), \
          "=r"((r)[20]), "=r"((r)[21]), "=r"((r)[22]), "=r"((r)[23]), \
          "=r"((r)[24]), "=r"((r)[25]), "=r"((r)[26]), "=r"((r)[27]), \
          "=r"((r)[28]), "=r"((r)[29]), "=r"((r)[30]), "=r"((r)[31]) \
        : "r"(addr))
#endif  // HAS_TCGEN05

// ============================================================================
// Conversion kernels (arch-neutral)
// ============================================================================

__global__ void __launch_bounds__(256) cvt_x_kernel(const float* __restrict__ x) {
    size_t i = ((size_t)blockIdx.x * blockDim.x + threadIdx.x) * 4;
    float4 v = *reinterpret_cast<const float4*>(x + i);
    *reinterpret_cast<__nv_bfloat162*>(&g_x[i])     = __floats2bfloat162_rn(v.x, v.y);
    *reinterpret_cast<__nv_bfloat162*>(&g_x[i + 2]) = __floats2bfloat162_rn(v.z, v.w);
}

__global__ void __launch_bounds__(256) cvt_w_kernel(const float* __restrict__ wq,
                                                    const float* __restrict__ sc) {
    size_t i = ((size_t)blockIdx.x * blockDim.x + threadIdx.x) * 4;
    int o = (int)(i >> 12);  // row = i / 4096
    __nv_bfloat16 s = __float2bfloat16(sc[o]);
    float4 v = *reinterpret_cast<const float4*>(wq + i);
    __nv_bfloat16 h0 = __hmul(__float2bfloat16(v.x), s);
    __nv_bfloat16 h1 = __hmul(__float2bfloat16(v.y), s);
    __nv_bfloat16 h2 = __hmul(__float2bfloat16(v.z), s);
    __nv_bfloat16 h3 = __hmul(__float2bfloat16(v.w), s);
    *reinterpret_cast<__nv_bfloat162*>(&g_w[i])     = __halves2bfloat162(h0, h1);
    *reinterpret_cast<__nv_bfloat162*>(&g_w[i + 2]) = __halves2bfloat162(h2, h3);
}

// ============================================================================
// GEMM kernel: 256x512 pair tile (cg2, 2 x N=256 dispatches), 4 stages, occ 1.
// ============================================================================

__global__ void __launch_bounds__(NTHREADS) __cluster_dims__(2, 1, 1)
gemm_kernel(float* __restrict__ out, const float* __restrict__ bias) {
    extern __shared__ char smem[];
    int tid = threadIdx.x;

#if HAS_TCGEN05
    uint32_t sb = smem_u32(smem);
    int wid = tid >> 5;
    int lid = tid & 31;
    uint32_t rank = ctarank();
    int n0t = (blockIdx.x >> 1) * NT;          // pair's N origin (512-wide)
    int m0t = blockIdx.y * MT;                 // pair's M origin (256-wide)

    if (tid == 0) {
        #pragma unroll
        for (int s = 0; s < STAGES; s++) {
            mbar_init(sb + SMEM_EMPTY + 8 * s, 1);     // MMA commit (multicast)
            mbar_init(sb + SMEM_FULL + 8 * s, 256);    // 128 loaders x 2 CTAs
        }
    }
    if (wid == 0) {
        TC_ALLOC_CG2(sb + SMEM_TMEM_PTR, 512);
    }
    __syncthreads();
    uint32_t tmem;
    asm volatile("ld.shared.b32 %0, [%1];" : "=r"(tmem) : "r"(sb + SMEM_TMEM_PTR));

    cluster_sync();

    if (wid < 4) {
        // ---------------- Loader role (threads 0..127) ----------------
        int lrow = tid >> 3;                   // 0..15
        int lcolb = (tid & 7) * 16;
        uint32_t swc[8];
        #pragma unroll
        for (int j = 0; j < 8; j++) {
            uint32_t off = (uint32_t)(lrow + j * 16) * 128 + lcolb;
            swc[j] = off ^ ((off >> 3) & 0x70);
        }
        // A: rows m0t + rank*128 + [0,128)
        const __nv_bfloat16* xbase =
            g_x + (size_t)(m0t + rank * 128 + lrow) * Kdim + (tid & 7) * 8;
        // B half0: N rows n0t + rank*128 + [0,128); half1: n0t + 256 + rank*128 + [0,128)
        const __nv_bfloat16* wbase0 =
            g_w + (size_t)(n0t + rank * 128 + lrow) * Kdim + (tid & 7) * 8;
        const __nv_bfloat16* wbase1 =
            g_w + (size_t)(n0t + 256 + rank * 128 + lrow) * Kdim + (tid & 7) * 8;

        auto load_chunk = [&](int c, int s) {
            uint32_t abase = sb + SMEM_A + s * A_STAGE;
            uint32_t bbase = sb + SMEM_B + s * B_STAGE;
            const __nv_bfloat16* xa = xbase + c * KC;
            const __nv_bfloat16* wb0 = wbase0 + c * KC;
            const __nv_bfloat16* wb1 = wbase1 + c * KC;
            #pragma unroll
            for (int j = 0; j < 8; j++) {
                cp_async16(abase + swc[j],                 xa  + (size_t)j * 16 * Kdim);
                cp_async16(bbase + swc[j],                 wb0 + (size_t)j * 16 * Kdim);
                cp_async16(bbase + A_STAGE + swc[j],       wb1 + (size_t)j * 16 * Kdim);
            }
            cp_commit();
        };

        // Prologue: fill stages 0..2 (3 chunks ahead).
        load_chunk(0, 0);
        load_chunk(1, 1);
        load_chunk(2, 2);

        for (int c = 0; c < NCHUNK; c++) {
            int buf = c % STAGES;
            // Reuse gate: buffer (c+3)%4 == (c-1)%4 was consumed by chunk c-1.
            if (c + 3 < NCHUNK) {
                if (c >= 1) {
                    mbar_wait(sb + SMEM_EMPTY + 8 * ((c - 1) % STAGES),
                              ((c - 1) / STAGES) & 1);
                }
                load_chunk(c + 3, (c + 3) % STAGES);
            }
            int rem = NCHUNK - 1 - c;
            if (rem >= 3)      cp_wait<3>();
            else if (rem == 2) cp_wait<2>();
            else if (rem == 1) cp_wait<1>();
            else               cp_wait<0>();
            fence_proxy_async_cta();
            mbar_arrive_cluster(sb + SMEM_FULL + 8 * buf, 0);
        }
    } else if (rank == 0) {
        // ---------------- MMA-issue role (warp 4, rank 0) ----------------
        if (elect_one()) {
            for (int c = 0; c < NCHUNK; c++) {
                int buf = c % STAGES;
                mbar_wait_cluster(sb + SMEM_FULL + 8 * buf, (c / STAGES) & 1);
                TC_FENCE_AFTER();
                uint64_t ad = make_desc(sb + SMEM_A + buf * A_STAGE);
                uint64_t bd = make_desc(sb + SMEM_B + buf * B_STAGE);
                #pragma unroll
                for (int kk = 0; kk < 4; kk++) {
                    uint32_t en = (c == 0 && kk == 0) ? 0u : 1u;
                    // Half 0: D cols [0,256) <- B group at stage offset 0
                    mma_f16_ss_cg2(tmem, ad + kk * 2, bd + kk * 2,
                                   IDESC_CG2, en);
                    // Half 1: D cols [256,512) <- B group at stage offset 16KB (1024 units)
                    mma_f16_ss_cg2(tmem + 256, ad + kk * 2, bd + 1024 + kk * 2,
                                   IDESC_CG2, en);
                }
                tc_commit_mcast_cg2(sb + SMEM_EMPTY + 8 * buf, 0x3);
            }
        }
    }

    // Final commit tracks all prior MMAs; delivered to both CTAs.
    mbar_wait(sb + SMEM_EMPTY + 8 * ((NCHUNK - 1) % STAGES), ((NCHUNK - 1) / STAGES) & 1);
    TC_FENCE_AFTER();

    // Epilogue (FP32): warps 0-3. Row = rank*128 + wid*32 + lid; 512 cols.
    if (wid < 4) {
        int mrow = m0t + (int)rank * 128 + wid * 32 + lid;
        float* orow = out + (size_t)mrow * Ndim + n0t;
        #pragma unroll
        for (int cb = 0; cb < NT; cb += 32) {
            uint32_t r[32];
            LDTM_X32(r, tmem + cb);
            TC_WAIT_LD();
            float vals[32];
            #pragma unroll
            for (int j = 0; j < 32; j++) {
                __nv_bfloat16 s = __hadd(__float2bfloat16(__uint_as_float(r[j])),
                                         __float2bfloat16(bias[n0t + cb + j]));
                vals[j] = __bfloat162float(s);
            }
            float4* dst = reinterpret_cast<float4*>(orow + cb);
            #pragma unroll
            for (int q = 0; q < 8; q++) {
                dst[q] = make_float4(vals[4 * q], vals[4 * q + 1],
                                     vals[4 * q + 2], vals[4 * q + 3]);
            }
        }
    }

    __syncthreads();
    if (tid == 0) {
        #pragma unroll
        for (int s = 0; s < STAGES; s++) {
            mbar_inval(sb + SMEM_EMPTY + 8 * s);
            mbar_inval(sb + SMEM_FULL + 8 * s);
        }
    }
    __syncthreads();
    if (wid == 0) {
        TC_RELINQUISH_CG2();
        TC_DEALLOC_CG2(tmem, 512);
    }
    cluster_sync();
#else
    // ---------- Generic fallback (no tcgen05 in this compile pass) ----------
    int rank = blockIdx.x & 1;
    int n0t = (blockIdx.x >> 1) * NT;
    int m0 = blockIdx.y * MT + rank * 128;

    for (int half = 0; half < 4; half++) {
        int n0 = n0t + half * 128;
        __nv_bfloat16* As = reinterpret_cast<__nv_bfloat16*>(smem);        // 128 x 32
        __nv_bfloat16* Bs = As + 128 * 32;                                 // 128 x 32
        int tr = tid >> 3;
        int tc = tid & 7;

        float acc[8][16];
        #pragma unroll
        for (int i = 0; i < 8; i++)
            #pragma unroll
            for (int j = 0; j < 16; j++) acc[i][j] = 0.0f;

        for (int kc = 0; kc < Kdim; kc += 32) {
            if (tid < 128) {
                const uint4* srcA = reinterpret_cast<const uint4*>(g_x + (size_t)(m0 + tid) * Kdim + kc);
                const uint4* srcB = reinterpret_cast<const uint4*>(g_w + (size_t)(n0 + tid) * Kdim + kc);
                uint4* dA = reinterpret_cast<uint4*>(As + tid * 32);
                uint4* dB = reinterpret_cast<uint4*>(Bs + tid * 32);
                #pragma unroll
                for (int j = 0; j < 4; j++) { dA[j] = srcA[j]; dB[j] = srcB[j]; }
            }
            __syncthreads();

            if (tid < 128) {
                for (int kk = 0; kk < 32; kk++) {
                    float a[8], b[16];
                    #pragma unroll
                    for (int i = 0; i < 8; i++)
                        a[i] = __bfloat162float(As[(tr * 8 + i) * 32 + kk]);
                    #pragma unroll
                    for (int j = 0; j < 16; j++)
                        b[j] = __bfloat162float(Bs[(tc * 16 + j) * 32 + kk]);
                    #pragma unroll
                    for (int i = 0; i < 8; i++)
                        #pragma unroll
                        for (int j = 0; j < 16; j++)
                            acc[i][j] = fmaf(a[i], b[j], acc[i][j]);
                }
            }
            __syncthreads();
        }

        if (tid < 128) {
            #pragma unroll
            for (int i = 0; i < 8; i++) {
                int m = m0 + tr * 8 + i;
                #pragma unroll
                for (int j = 0; j < 16; j++) {
                    int n = n0 + tc * 16 + j;
                    __nv_bfloat16 v = __hadd(__float2bfloat16(acc[i][j]),
                                             __float2bfloat16(bias[n]));
                    out[(size_t)m * Ndim + n] = __bfloat162float(v);
                }
            }
        }
        __syncthreads();
    }
#endif
}

// ============================================================================
// Launch
// ============================================================================

extern "C" void kernel_launch(void* const* d_in, const int* in_sizes, int n_in,
                              void* d_out, int out_size) {
    const float* x    = (const float*)d_in[0];   // [B, S, IN] f32
    const float* wq   = (const float*)d_in[1];   // [OUT, IN] f32 (fp8-representable)
    const float* ws   = (const float*)d_in[2];   // [OUT, 1] f32
    const float* bias = (const float*)d_in[3];   // [OUT] f32
    float* out = (float*)d_out;                  // [B, S, OUT] FP32

    // Convert inputs to bf16 scratch.
    {
        int threads = 256;
        int blocks = (Mdim * Kdim / 4) / threads;  // 16384
        cvt_x_kernel<<<blocks, threads>>>(x);
        cvt_w_kernel<<<blocks, threads>>>(wq, ws);
    }

    cudaFuncSetAttribute(gemm_kernel, cudaFuncAttributeMaxDynamicSharedMemorySize, SMEM_TOTAL);
    // Grid: x = 2 CTAs/pair * 8 n-tiles = 16, y = 16 m-tiles; cluster (2,1,1).
    dim3 grid(2 * (Ndim / NT), Mdim / MT);  // (16, 16) = 256 CTAs
    gemm_kernel<<<grid, NTHREADS, SMEM_TOTAL>>>(out, bias);
}

// round 17
// speedup vs baseline: 1.6466x; 1.3589x over previous
#include <cuda_runtime.h>
#include <cuda_bf16.h>
#include <cstdint>

// ============================================================================
// out_f32[m, n] = f32( bf16(sum_k bf16(x[m,k]) * (bf16(w_fp8[n,k])*bf16(sc[n]))) + bf16(bias[n]) )
// M = B*S = 4096, N = OUT = 4096, K = IN = 4096. OUTPUT FP32.
// R15 (189us) is L2-traffic bound. This round: cluster (4,1,1) = two cg2 pairs
// on a 512x512 supertile; B multicast across pairs (CTA0->{0,2}, CTA1->{1,3})
// via cp.async.bulk.multicast -> chip traffic 768 -> 512 MB.
// Converts write g_x/g_w in TILED layout: [row128-group][K-chunk] -> contiguous
// 16KB SW128-swizzled tile, so each stage load is ONE 16KB bulk copy.
// tcgen05/bulk-multicast only in the arch-specific pass; generic pass gets a
// correct scalar fallback reading the tiled layout.
// ============================================================================

#if defined(__CUDA_ARCH__) && \
    (defined(__CUDA_ARCH_FEAT_SM103_ALL) || defined(__CUDA_ARCH_FEAT_SM100_ALL) || \
     defined(__CUDA_ARCH_FEAT_SM101_ALL) || defined(__CUDA_ARCH_SPECIFIC__) || \
     defined(__CUDA_ARCH_FAMILY_SPECIFIC__))
#define HAS_TCGEN05 1
#else
#define HAS_TCGEN05 0
#endif

static constexpr int Mdim = 4096, Ndim = 4096, Kdim = 4096;
static constexpr int NT = 512;                            // supertile N (and M)
static constexpr int KC = 64;                             // K chunk: 64 bf16 = 128B rows
static constexpr int STAGES = 4;
static constexpr int NCHUNK = Kdim / KC;                  // 64
static constexpr int TILE_BYTES = 128 * 128;              // 16KB: 128 rows x 128B
static constexpr int A_STAGE = TILE_BYTES;                // 16KB per CTA
static constexpr int B_STAGE = 2 * TILE_BYTES;            // 32KB per CTA (2 groups)
static constexpr int NTHREADS = 128;

static constexpr int SMEM_TMEM_PTR = 0;
static constexpr int SMEM_EMPTY = 64;                     // 4 x 8B, count=2 (both leaders)
static constexpr int SMEM_FULL = 96;                      // 4 x 8B, count=1, expect_tx 48KB
static constexpr int SMEM_READY = 128;                    // 4 x 8B, count=2 (pair watchers)
static constexpr int SMEM_A = 1024;
static constexpr int SMEM_B = SMEM_A + STAGES * A_STAGE;          // +64KB
static constexpr int SMEM_TOTAL = SMEM_B + STAGES * B_STAGE;      // ~193KB -> 1 CTA/SM

// idesc kind::f16 cg2, N=256 per dispatch, M=256.
static constexpr uint32_t IDESC_CG2 =
    (1u << 4) | (1u << 7) | (1u << 10) | ((256 / 8) << 17) | ((256 / 16) << 24);

// bf16 scratch in TILED layout: tile t = rowGroup*64 + chunk, 16KB each.
__device__ __align__(1024) __nv_bfloat16 g_x[(size_t)Mdim * Kdim];
__device__ __align__(1024) __nv_bfloat16 g_w[(size_t)Ndim * Kdim];

// Byte offset of element (row128grp, row in 0..127, k) in the tiled layout.
__device__ __forceinline__ size_t tiled_off(int grp, int row, int k) {
    size_t tile = (size_t)grp * 64 + (k >> 6);
    uint32_t inner = (uint32_t)row * 128 + (uint32_t)(k & 63) * 2;
    inner ^= ((inner >> 3) & 0x70);
    return tile * TILE_BYTES + inner;
}

// Pack two bf16 (lo, hi) into a uint32.
__device__ __forceinline__ uint32_t pack_bf2(__nv_bfloat162 v) {
    return ((uint32_t)__bfloat16_as_ushort(__high2bfloat16(v)) << 16) |
           (uint32_t)__bfloat16_as_ushort(__low2bfloat16(v));
}

// ============================================================================
// PTX helpers
// ============================================================================

__device__ __forceinline__ uint32_t smem_u32(const void* p) {
    uint32_t a;
    asm("{ .reg .u64 t; cvta.to.shared.u64 t, %1; cvt.u32.u64 %0, t; }"
        : "=r"(a) : "l"(p));
    return a;
}

__device__ __forceinline__ uint32_t ctarank() {
    uint32_t r;
    asm("mov.u32 %0, %%cluster_ctarank;" : "=r"(r));
    return r;
}

__device__ __forceinline__ void cluster_sync() {
    asm volatile("barrier.cluster.arrive.aligned;" ::: "memory");
    asm volatile("barrier.cluster.wait.aligned;" ::: "memory");
}

#if HAS_TCGEN05
__device__ __forceinline__ uint32_t elect_one() {
    uint32_t pred;
    asm volatile(
        "{\n\t.reg .pred p;\n\t"
        "elect.sync _|p, 0xFFFFFFFF;\n\t"
        "selp.b32 %0, 1, 0, p;\n\t}"
        : "=r"(pred));
    return pred;
}

__device__ __forceinline__ void mbar_init(uint32_t addr, uint32_t count) {
    asm volatile("mbarrier.init.shared.b64 [%0], %1;" :: "r"(addr), "r"(count) : "memory");
}
__device__ __forceinline__ void mbar_inval(uint32_t addr) {
    asm volatile("mbarrier.inval.shared.b64 [%0];" :: "r"(addr) : "memory");
}
__device__ __forceinline__ void mbar_expect_tx(uint32_t addr, uint32_t bytes) {
    asm volatile("mbarrier.arrive.expect_tx.shared.b64 _, [%0], %1;"
                 :: "r"(addr), "r"(bytes) : "memory");
}
__device__ __forceinline__ void mbar_wait(uint32_t addr, uint32_t parity) {
    asm volatile(
        "{\n\t.reg .pred P;\n\t"
        "WAIT_%=:\n\t"
        "mbarrier.try_wait.parity.acquire.cta.shared::cta.b64 P, [%0], %1, 0x989680;\n\t"
        "@P bra DONE_%=;\n\t"
        "bra WAIT_%=;\n\t"
        "DONE_%=:\n\t}"
        :: "r"(addr), "r"(parity) : "memory");
}
__device__ __forceinline__ void mbar_wait_cluster(uint32_t addr, uint32_t parity) {
    asm volatile(
        "{\n\t.reg .pred P;\n\t"
        "WAIT_%=:\n\t"
        "mbarrier.try_wait.parity.acquire.cluster.shared::cta.b64 P, [%0], %1, 0x989680;\n\t"
        "@P bra DONE_%=;\n\t"
        "bra WAIT_%=;\n\t"
        "DONE_%=:\n\t}"
        :: "r"(addr), "r"(parity) : "memory");
}
// Arrive on the mbarrier at the same SMEM offset in cluster CTA `target_rank`.
__device__ __forceinline__ void mbar_arrive_cluster(uint32_t local_addr, uint32_t target_rank) {
    asm volatile(
        "{\n\t.reg .b32 ra;\n\t"
        "mapa.shared::cluster.u32 ra, %0, %1;\n\t"
        "mbarrier.arrive.shared::cluster.b64 _, [ra];\n\t}"
        :: "r"(local_addr), "r"(target_rank) : "memory");
}

// Bulk 16KB-granule copies, global -> (cluster) shared, mbarrier completion.
__device__ __forceinline__ void bulk_g2s(uint32_t dst, const void* src,
                                         uint32_t bytes, uint32_t mbar) {
    asm volatile(
        "cp.async.bulk.shared::cluster.global.mbarrier::complete_tx::bytes "
        "[%0], [%1], %2, [%3];"
        :: "r"(dst), "l"(src), "r"(bytes), "r"(mbar) : "memory");
}
__device__ __forceinline__ void bulk_g2s_mc(uint32_t dst, const void* src,
                                            uint32_t bytes, uint32_t mbar,
                                            uint16_t mask) {
    asm volatile(
        "cp.async.bulk.shared::cluster.global.mbarrier::complete_tx::bytes.multicast::cluster "
        "[%0], [%1], %2, [%3], %4;"
        :: "r"(dst), "l"(src), "r"(bytes), "r"(mbar), "h"(mask) : "memory");
}

// SW128 K-major descriptor: layout=2, version=1, SBO=64, LBO=1
__device__ __forceinline__ uint64_t make_desc(uint32_t addr) {
    const uint64_t base =
        (uint64_t(2) << 61) | (uint64_t(1) << 46) | (uint64_t(64) << 32) | (uint64_t(1) << 16);
    return base | ((uint64_t)(addr >> 4) & 0x3FFF);
}

__device__ __forceinline__ void mma_f16_ss_cg2(uint32_t d_tmem, uint64_t a_desc,
                                               uint64_t b_desc, uint32_t idesc,
                                               uint32_t enable) {
    asm volatile(
        "{\n\t.reg .pred p;\n\t"
        "setp.ne.u32 p, %6, 0;\n\t"
        "tcgen05.mma.cta_group::2.kind::f16 [%0], %1, %2, %3, "
        "{%4, %4, %4, %4, %4, %4, %4, %4}, p;\n\t}"
        :: "r"(d_tmem), "l"(a_desc), "l"(b_desc), "r"(idesc),
           "r"(0u), "r"(0u), "r"(enable)
        : "memory");
}

__device__ __forceinline__ void tc_commit_mcast_cg2(uint32_t mbar, uint16_t mask) {
    asm volatile(
        "tcgen05.commit.cta_group::2.mbarrier::arrive::one.shared::cluster.multicast::cluster.b64 [%0], %1;"
        :: "r"(mbar), "h"(mask) : "memory");
}

#define TC_ALLOC_CG2(smem_addr, ncols) \
    asm volatile("tcgen05.alloc.cta_group::2.sync.aligned.shared::cta.b32 [%0], %1;" \
                 :: "r"(smem_addr), "r"((uint32_t)(ncols)) : "memory")
#define TC_DEALLOC_CG2(tmem, ncols) \
    asm volatile("tcgen05.dealloc.cta_group::2.sync.aligned.b32 %0, %1;" \
                 :: "r"(tmem), "r"((uint32_t)(ncols)))
#define TC_RELINQUISH_CG2() \
    asm volatile("tcgen05.relinquish_alloc_permit.cta_group::2.sync.aligned;")
#define TC_FENCE_AFTER() asm volatile("tcgen05.fence::after_thread_sync;" ::: "memory")
#define TC_WAIT_LD() asm volatile("tcgen05.wait::ld.sync.aligned;" ::: "memory")

#define LDTM_X32(r, addr) \
    asm volatile( \
        "tcgen05.ld.sync.aligned.32x32b.x32.b32 " \
        "{%0, %1, %2, %3, %4, %5, %6, %7, " \
        " %8, %9, %10, %11, %12, %13, %14, %15, " \
        " %16, %17, %18, %19, %20, %21, %22, %23, " \
        " %24, %25, %26, %27, %28, %29, %30, %31}, [%32];" \
        : "=r"((r)[0]),  "=r"((r)[1]),  "=r"((r)[2]),  "=r"((r)[3]), \
          "=r"((r)[4]),  "=r"((r)[5]),  "=r"((r)[6]),  "=r"((r)[7]), \
          "=r"((r)[8]),  "=r"((r)[9]),  "=r"((r)[10]), "=r"((r)[11]), \
          "=r"((r)[12]), "=r"((r)[13]), "=r"((r)[14]), "=r"((r)[15]), \
          "=r"((r)[16]), "=r"((r)[17]), "=r"((r)[18]), "=r"((r)[19]), \
          "=r"((r)[20]), "=r"((r)[21]), "=r"((r)[22]), "=r"((r)[23]), \
          "=r"((r)[24]), "=r"((r)[25]), "=r"((r)[26]), "=r"((r)[27]), \
          "=r"((r)[28]), "=r"((r)[29]), "=r"((r)[30]), "=r"((r)[31]) \
        : "r"(addr))
#endif  // HAS_TCGEN05

// ============================================================================
// Conversion kernels: f32 -> bf16, TILED+SWIZZLED layout. Each thread handles
// 8 consecutive k (one 16B swizzle slot).
// ============================================================================

__global__ void __launch_bounds__(256) cvt_x_kernel(const float* __restrict__ x) {
    size_t e = ((size_t)blockIdx.x * blockDim.x + threadIdx.x) * 8;
    int m = (int)(e >> 12);
    int k = (int)(e & 4095);
    const float4* p = reinterpret_cast<const float4*>(x + e);
    float4 v0 = p[0], v1 = p[1];
    uint4 o;
    o.x = pack_bf2(__floats2bfloat162_rn(v0.x, v0.y));
    o.y = pack_bf2(__floats2bfloat162_rn(v0.z, v0.w));
    o.z = pack_bf2(__floats2bfloat162_rn(v1.x, v1.y));
    o.w = pack_bf2(__floats2bfloat162_rn(v1.z, v1.w));
    *reinterpret_cast<uint4*>(reinterpret_cast<char*>(g_x) +
                              tiled_off(m >> 7, m & 127, k)) = o;
}

__global__ void __launch_bounds__(256) cvt_w_kernel(const float* __restrict__ wq,
                                                    const float* __restrict__ sc) {
    size_t e = ((size_t)blockIdx.x * blockDim.x + threadIdx.x) * 8;
    int ow = (int)(e >> 12);
    int k = (int)(e & 4095);
    __nv_bfloat16 s = __float2bfloat16(sc[ow]);
    __nv_bfloat162 s2 = __halves2bfloat162(s, s);
    const float4* p = reinterpret_cast<const float4*>(wq + e);
    float4 v0 = p[0], v1 = p[1];
    uint4 o;
    o.x = pack_bf2(__hmul2(__floats2bfloat162_rn(v0.x, v0.y), s2));
    o.y = pack_bf2(__hmul2(__floats2bfloat162_rn(v0.z, v0.w), s2));
    o.z = pack_bf2(__hmul2(__floats2bfloat162_rn(v1.x, v1.y), s2));
    o.w = pack_bf2(__hmul2(__floats2bfloat162_rn(v1.z, v1.w), s2));
    *reinterpret_cast<uint4*>(reinterpret_cast<char*>(g_w) +
                              tiled_off(ow >> 7, ow & 127, k)) = o;
}

// ============================================================================
// GEMM kernel: 512x512 supertile per 4-CTA cluster (two cg2 pairs), B
// multicast across pairs, bulk-copy loads, warp-specialized roles.
// ============================================================================

__global__ void __launch_bounds__(NTHREADS) __cluster_dims__(4, 1, 1)
gemm_kernel(float* __restrict__ out, const float* __restrict__ bias) {
    extern __shared__ char smem[];
    int tid = threadIdx.x;

#if HAS_TCGEN05
    uint32_t sb = smem_u32(smem);
    int wid = tid >> 5;
    int lid = tid & 31;
    uint32_t rank = ctarank();
    int pair = (int)(rank >> 1);               // 0 or 1 (M halves)
    int rb = (int)(rank & 1);                  // B-half ownership within pair
    int n0t = (blockIdx.x >> 2) * NT;          // supertile N origin (512)
    int m_super = blockIdx.y * 512;            // supertile M origin

    if (tid == 0) {
        #pragma unroll
        for (int s = 0; s < STAGES; s++) {
            mbar_init(sb + SMEM_EMPTY + 8 * s, 2);   // commits from both pair leaders
            mbar_init(sb + SMEM_FULL + 8 * s, 1);    // local expect_tx arrive
            mbar_init(sb + SMEM_READY + 8 * s, 2);   // pair's two watchers
        }
    }
    if (wid == 0) {
        TC_ALLOC_CG2(sb + SMEM_TMEM_PTR, 512);
    }
    __syncthreads();
    uint32_t tmem;
    asm volatile("ld.shared.b32 %0, [%1];" : "=r"(tmem) : "r"(sb + SMEM_TMEM_PTR));

    cluster_sync();

    // This CTA's A row-group and B groups.
    int msg = (m_super >> 7) + pair * 2 + rb;        // A 128-row group index
    int ng0 = (n0t >> 7) + rb;                       // B group for N-half 0
    int ng1 = ng0 + 2;                               // B group for N-half 1
    const char* gx = reinterpret_cast<const char*>(g_x);
    const char* gw = reinterpret_cast<const char*>(g_w);

    if (wid == 0) {
        // ---------------- Load-issuer (1 thread per CTA) ----------------
        if (elect_one()) {
            for (int c = 0; c < NCHUNK; c++) {
                int s = c & 3;
                int p = c >> 2;
                uint32_t full = sb + SMEM_FULL + 8 * s;
                if (p > 0) mbar_wait(sb + SMEM_EMPTY + 8 * s, (p - 1) & 1);
                mbar_expect_tx(full, 3 * TILE_BYTES);  // A 16KB + B 32KB
                // A: own 128 rows, local delivery.
                bulk_g2s(sb + SMEM_A + s * A_STAGE,
                         gx + ((size_t)msg * 64 + c) * TILE_BYTES,
                         TILE_BYTES, full);
                // B: ranks 0,1 load and multicast to {self, self+2}.
                if (pair == 0) {
                    uint16_t mask = (uint16_t)(0x5 << rb);  // rb=0 -> 0x5, rb=1 -> 0xA
                    bulk_g2s_mc(sb + SMEM_B + s * B_STAGE,
                                gw + ((size_t)ng0 * 64 + c) * TILE_BYTES,
                                TILE_BYTES, full, mask);
                    bulk_g2s_mc(sb + SMEM_B + s * B_STAGE + TILE_BYTES,
                                gw + ((size_t)ng1 * 64 + c) * TILE_BYTES,
                                TILE_BYTES, full, mask);
                }
            }
            // Final phase-synchronized wait: issuer tracked all empty phases.
            mbar_wait(sb + SMEM_EMPTY + 8 * ((NCHUNK - 1) & 3),
                      ((NCHUNK - 1) >> 2) & 1);
        }
    } else if (wid == 1) {
        // ---------------- Watcher: forward full -> pair leader's ready ------
        if (elect_one()) {
            for (int c = 0; c < NCHUNK; c++) {
                int s = c & 3;
                int p = c >> 2;
                mbar_wait(sb + SMEM_FULL + 8 * s, p & 1);
                mbar_arrive_cluster(sb + SMEM_READY + 8 * s, rank & 2u);
            }
        }
    } else if (wid == 2 && rb == 0) {
        // ---------------- MMA-issuer (pair leaders, ranks 0 and 2) ----------
        if (elect_one()) {
            for (int c = 0; c < NCHUNK; c++) {
                int s = c & 3;
                int p = c >> 2;
                mbar_wait_cluster(sb + SMEM_READY + 8 * s, p & 1);
                TC_FENCE_AFTER();
                uint64_t ad = make_desc(sb + SMEM_A + s * A_STAGE);
                uint64_t bd = make_desc(sb + SMEM_B + s * B_STAGE);
                #pragma unroll
                for (int kk = 0; kk < 4; kk++) {
                    uint32_t en = (c == 0 && kk == 0) ? 0u : 1u;
                    mma_f16_ss_cg2(tmem,       ad + kk * 2, bd + kk * 2,
                                   IDESC_CG2, en);
                    mma_f16_ss_cg2(tmem + 256, ad + kk * 2, bd + 1024 + kk * 2,
                                   IDESC_CG2, en);
                }
                tc_commit_mcast_cg2(sb + SMEM_EMPTY + 8 * s, 0xF);
            }
        }
    }

    // The issuer's final empty-wait guarantees all MMAs (both pairs) are done
    // before it joins this barrier.
    __syncthreads();
    TC_FENCE_AFTER();

    // Epilogue (FP32): row = m_super + pair*256 + rb*128 + wid*32 + lid; 512 cols.
    {
        int mrow = m_super + pair * 256 + rb * 128 + wid * 32 + lid;
        float* orow = out + (size_t)mrow * Ndim + n0t;
        #pragma unroll
        for (int cb = 0; cb < NT; cb += 32) {
            uint32_t r[32];
            LDTM_X32(r, tmem + cb);
            TC_WAIT_LD();
            float vals[32];
            #pragma unroll
            for (int j = 0; j < 32; j++) {
                __nv_bfloat16 s = __hadd(__float2bfloat16(__uint_as_float(r[j])),
                                         __float2bfloat16(bias[n0t + cb + j]));
                vals[j] = __bfloat162float(s);
            }
            float4* dst = reinterpret_cast<float4*>(orow + cb);
            #pragma unroll
            for (int q = 0; q < 8; q++) {
                dst[q] = make_float4(vals[4 * q], vals[4 * q + 1],
                                     vals[4 * q + 2], vals[4 * q + 3]);
            }
        }
    }

    __syncthreads();
    if (tid == 0) {
        #pragma unroll
        for (int s = 0; s < STAGES; s++) {
            mbar_inval(sb + SMEM_EMPTY + 8 * s);
            mbar_inval(sb + SMEM_FULL + 8 * s);
            mbar_inval(sb + SMEM_READY + 8 * s);
        }
    }
    __syncthreads();
    if (wid == 0) {
        TC_RELINQUISH_CG2();
        TC_DEALLOC_CG2(tmem, 512);
    }
    cluster_sync();
#else
    // ---------- Generic fallback (correct, slow; never runs on sm_103a) -----
    int rank = blockIdx.x & 3;
    int pair = rank >> 1;
    int rb = rank & 1;
    int n0t = (blockIdx.x >> 2) * NT;
    int m_super = blockIdx.y * 512;
    int mrow = m_super + pair * 256 + rb * 128 + tid;  // 128 threads = 128 rows

    const char* gx = reinterpret_cast<const char*>(g_x);
    const char* gw = reinterpret_cast<const char*>(g_w);
    for (int n = 0; n < NT; n++) {
        int ncol = n0t + n;
        float acc = 0.0f;
        for (int k = 0; k < Kdim; k++) {
            float a = __bfloat162float(*reinterpret_cast<const __nv_bfloat16*>(
                gx + tiled_off(mrow >> 7, mrow & 127, k)));
            float b = __bfloat162float(*reinterpret_cast<const __nv_bfloat16*>(
                gw + tiled_off(ncol >> 7, ncol & 127, k)));
            acc = fmaf(a, b, acc);
        }
        __nv_bfloat16 v = __hadd(__float2bfloat16(acc), __float2bfloat16(bias[ncol]));
        out[(size_t)mrow * Ndim + ncol] = __bfloat162float(v);
    }
#endif
}

// ============================================================================
// Launch
// ============================================================================

extern "C" void kernel_launch(void* const* d_in, const int* in_sizes, int n_in,
                              void* d_out, int out_size) {
    const float* x    = (const float*)d_in[0];   // [B, S, IN] f32
    const float* wq   = (const float*)d_in[1];   // [OUT, IN] f32 (fp8-representable)
    const float* ws   = (const float*)d_in[2];   // [OUT, 1] f32
    const float* bias = (const float*)d_in[3];   // [OUT] f32
    float* out = (float*)d_out;                  // [B, S, OUT] FP32

    // Convert inputs to bf16 tiled scratch.
    {
        int threads = 256;
        int blocks = (int)(((size_t)Mdim * Kdim / 8) / threads);  // 8192
        cvt_x_kernel<<<blocks, threads>>>(x);
        cvt_w_kernel<<<blocks, threads>>>(wq, ws);
    }

    cudaFuncSetAttribute(gemm_kernel, cudaFuncAttributeMaxDynamicSharedMemorySize, SMEM_TOTAL);
    // Grid: x = 4 CTAs/cluster * 8 n-supertiles = 32, y = 8 m-supertiles.
    dim3 grid(4 * (Ndim / NT), Mdim / 512);  // (32, 8) = 256 CTAs
    gemm_kernel<<<grid, NTHREADS, SMEM_TOTAL>>>(out, bias);
}